// round 12
// baseline (speedup 1.0000x reference)
#include <cuda_runtime.h>
#include <cuda_fp16.h>
#include <cstdint>

#define TT        10
#define NB        32
#define THREADS   512
#define NCTA      (65536 / NB)       // 2048

// smem layout (bytes)
#define XSH_OFF   0                  // hi planes: 256 k-rows x 32 n x 2B = 16KB each
#define XIH_OFF   16384
#define XRH_OFF   32768
#define XRL_OFF   49152              // state lo planes (xr, xi)
#define XIL_OFF   65536
#define KB1_OFF   81920              // k1: 256 x 32 fp32 (scol-shifted)
#define KB2_OFF   114688             // k2
#define YSL_OFF   131072             // pass-0 ys-lo, aliased into upper half of KB2
#define AYR_OFF   147456             // Ay fp32
#define AYI_OFF   180224
#define SMEM_TOTAL 212992            // 208KB

// Gauss-stacked weights, MMA fragment order:
// uint4 index ((chunk16*48 + gmt)*32 + lane); gmt [0,48): m 0-255 Br, 256-511 Br+Bi, 512-767 Bi-Br
__device__ __half g_WBH[196608];   // 384KB (16 chunks x 48 mtiles)
__device__ __half g_WBL[196608];
__device__ __half g_WAH[98304];    // 192KB (8 chunks x 48 mtiles)
__device__ __half g_WAL[98304];

// ---------------- PTX helpers ----------------
static __device__ __forceinline__ uint32_t smem_u32(const void* p) {
    uint32_t a;
    asm("{ .reg .u64 t; cvta.to.shared.u64 t, %1; cvt.u32.u64 %0, t; }" : "=r"(a) : "l"(p));
    return a;
}
static __device__ __forceinline__ void ldmB4(uint32_t* r, uint32_t addr) {
    asm volatile("ldmatrix.sync.aligned.m8n8.x4.trans.shared.b16 {%0,%1,%2,%3}, [%4];"
                 : "=r"(r[0]), "=r"(r[1]), "=r"(r[2]), "=r"(r[3]) : "r"(addr));
}
static __device__ __forceinline__ void mma16816(float* d, const uint32_t* a, const uint32_t* b) {
    asm volatile("mma.sync.aligned.m16n8k16.row.col.f32.f16.f16.f32 "
                 "{%0,%1,%2,%3}, {%4,%5,%6,%7}, {%8,%9}, {%0,%1,%2,%3};"
                 : "+f"(d[0]), "+f"(d[1]), "+f"(d[2]), "+f"(d[3])
                 : "r"(a[0]), "r"(a[1]), "r"(a[2]), "r"(a[3]), "r"(b[0]), "r"(b[1]));
}
// Swizzle for 64B rows (hi/lo planes)
static __device__ __host__ __forceinline__ uint32_t swz64(int row, int colbyte) {
    return (uint32_t)(row * 64 + (colbyte ^ ((row & 6) << 3)));
}
// fp32 scratch column shift: word index within a 32-word row
static __device__ __forceinline__ uint32_t scol(int m, int n0) {
    return (uint32_t)((n0 + ((m & 3) << 3)) & 31);
}

// ---------------- prep: Gauss-stacked W', fp16 hi/lo fragment order ----------------
__global__ void prep_kernel(const float* __restrict__ A, const float* __restrict__ B) {
    const int NBEL = 768 * 256, NAEL = 768 * 128;
    for (int i = blockIdx.x * blockDim.x + threadIdx.x; i < NBEL + NAEL;
         i += gridDim.x * blockDim.x) {
        int R, k;
        float w;
        __half *dH, *dL;
        if (i < NBEL) {
            R = i >> 8; k = i & 255;
            const int grp = R >> 8, m = R & 255;
            const float br = B[m * 256 + k], bi = B[65536 + m * 256 + k];
            w = (grp == 0) ? br : ((grp == 1) ? br + bi : bi - br);
            dH = g_WBH; dL = g_WBL;
        } else {
            const int j = i - NBEL;
            R = j >> 7; k = j & 127;
            const int grp = R >> 8, m = R & 255;
            const float ar = A[m * 128 + k], ai = A[32768 + m * 128 + k];
            w = (grp == 0) ? ar : ((grp == 1) ? ar + ai : ai - ar);
            dH = g_WAH; dL = g_WAL;
        }
        const int gmt = R >> 4, row = R & 15, chunk = k >> 4, kk = k & 15;
        const int rr = (row >> 3) | ((kk >> 3) << 1);
        const int t = (kk & 7) >> 1, pos = kk & 1;
        const int lane = (row & 7) * 4 + t;
        const int dest = ((chunk * 48 + gmt) * 32 + lane) * 8 + rr * 2 + pos;
        __half hi = __float2half_rn(w);
        dH[dest] = hi;
        dL[dest] = __float2half_rn(w - __half2float(hi));
    }
}

// ---------------- merged sweep: 3 mtiles/warp, one K-loop, per-warp K-phase stagger ----------------
// acc[12][4]: [0..7] = k1-or-k2 (gmtA, gmtA+1); [8..11] = k3 (gmt3)
static __device__ __forceinline__ void sweep(
    const char* smc, const __half* gHh, const __half* gLh, int NC, bool term3,
    uint32_t p1hi, uint32_t p1lo, float (*acc)[4], int gmtA, int gmt3, int lane, int coff)
{
    const uint4* gH = (const uint4*)gHh;
    const uint4* gL = (const uint4*)gLh;
    const uint32_t smb = smem_u32(smc);
    const uint32_t bxor = (uint32_t)((lane & 6) << 3);
    const uint32_t brow = ((uint32_t)(lane & 7) + ((uint32_t)((lane >> 3) & 1)) * 8) * 64;
    const uint32_t bcol0 = (((uint32_t)(lane >> 4) * 16)) ^ bxor;
    const uint32_t bcol1 = (32u + (uint32_t)(lane >> 4) * 16) ^ bxor;
    const int CS = 48 * 32;
    const int cmask = NC - 1;        // NC is 8 or 16 (power of two)

#pragma unroll
    for (int i = 0; i < 12; ++i)
#pragma unroll
        for (int j = 0; j < 4; ++j) acc[i][j] = 0.0f;

    const int iA = gmtA * 32 + lane, i3 = gmt3 * 32 + lane;
    uint4 A0[6], A1[6];
    {
        const int c0 = coff & cmask, c1 = (coff + 1) & cmask;
        A0[0] = __ldg(gH + iA + c0 * CS); A0[1] = __ldg(gH + iA + c0 * CS + 32);
        A0[2] = __ldg(gH + i3 + c0 * CS);
        A0[3] = __ldg(gL + iA + c0 * CS); A0[4] = __ldg(gL + iA + c0 * CS + 32);
        A0[5] = __ldg(gL + i3 + c0 * CS);
        A1[0] = __ldg(gH + iA + c1 * CS); A1[1] = __ldg(gH + iA + c1 * CS + 32);
        A1[2] = __ldg(gH + i3 + c1 * CS);
        A1[3] = __ldg(gL + iA + c1 * CS); A1[4] = __ldg(gL + iA + c1 * CS + 32);
        A1[5] = __ldg(gL + i3 + c1 * CS);
    }

#pragma unroll 1
    for (int c = 0; c < NC; c += 2) {
#pragma unroll
        for (int half = 0; half < 2; ++half) {
            const uint4* Ar = half ? A1 : A0;
            const int cc = (c + half + coff) & cmask;
            const uint32_t co = (uint32_t)cc << 10;
            // ---- plane 1 (k1 or k2 operand) ----
            {
                uint32_t bh[8];
                ldmB4(bh,     smb + p1hi + co + brow + bcol0);
                ldmB4(bh + 4, smb + p1hi + co + brow + bcol1);
#pragma unroll
                for (int nt = 0; nt < 4; ++nt) {
                    mma16816(acc[nt],     (const uint32_t*)&Ar[0], &bh[nt * 2]); // Wh*xh
                    mma16816(acc[4 + nt], (const uint32_t*)&Ar[1], &bh[nt * 2]);
                }
#pragma unroll
                for (int nt = 0; nt < 4; ++nt) {
                    mma16816(acc[nt],     (const uint32_t*)&Ar[3], &bh[nt * 2]); // Wl*xh
                    mma16816(acc[4 + nt], (const uint32_t*)&Ar[4], &bh[nt * 2]);
                }
                if (term3) {
                    uint32_t bl[8];
                    ldmB4(bl,     smb + p1lo + co + brow + bcol0);
                    ldmB4(bl + 4, smb + p1lo + co + brow + bcol1);
#pragma unroll
                    for (int nt = 0; nt < 4; ++nt) {
                        mma16816(acc[nt],     (const uint32_t*)&Ar[0], &bl[nt * 2]); // Wh*xl
                        mma16816(acc[4 + nt], (const uint32_t*)&Ar[1], &bl[nt * 2]);
                    }
                }
            }
            // ---- plane 3 (xr, k3 operand) ----
            {
                uint32_t b3[8];
                ldmB4(b3,     smb + XRH_OFF + co + brow + bcol0);
                ldmB4(b3 + 4, smb + XRH_OFF + co + brow + bcol1);
#pragma unroll
                for (int nt = 0; nt < 4; ++nt)
                    mma16816(acc[8 + nt], (const uint32_t*)&Ar[2], &b3[nt * 2]);
#pragma unroll
                for (int nt = 0; nt < 4; ++nt)
                    mma16816(acc[8 + nt], (const uint32_t*)&Ar[5], &b3[nt * 2]);
                if (term3) {
                    uint32_t b3l[8];
                    ldmB4(b3l,     smb + XRL_OFF + co + brow + bcol0);
                    ldmB4(b3l + 4, smb + XRL_OFF + co + brow + bcol1);
#pragma unroll
                    for (int nt = 0; nt < 4; ++nt)
                        mma16816(acc[8 + nt], (const uint32_t*)&Ar[2], &b3l[nt * 2]);
                }
            }
            // prefetch this buffer's next chunk (staggered index)
            const int pf = c + half + 2;
            if (pf < NC) {
                const int pcc = (pf + coff) & cmask;
                uint4* Aw = half ? A1 : A0;
                Aw[0] = __ldg(gH + iA + pcc * CS); Aw[1] = __ldg(gH + iA + pcc * CS + 32);
                Aw[2] = __ldg(gH + i3 + pcc * CS);
                Aw[3] = __ldg(gL + iA + pcc * CS); Aw[4] = __ldg(gL + iA + pcc * CS + 32);
                Aw[5] = __ldg(gL + i3 + pcc * CS);
            }
        }
    }
}

// ---------------- main fused kernel ----------------
__global__ __launch_bounds__(THREADS, 1)
void lista_main(const float* __restrict__ y,
                const float* __restrict__ etas,
                const float* __restrict__ gammas,
                float* __restrict__ out) {
    extern __shared__ char smc[];
    const int tid = threadIdx.x, lane = tid & 31, wid = tid >> 5;
    const long b0 = (long)blockIdx.x * NB;

    // stage y: yr -> XRH/XRL, yi -> XIH/XIL, yr+yi -> XSH + YSL(lo)
    const float2* y2 = (const float2*)y;
    for (int idx = tid; idx < NB * 128; idx += THREADS) {
        const int n = idx >> 7, q = idx & 127;
        const float2 v = y2[(b0 + n) * 128 + q];
        const uint32_t off = swz64(q, n * 2);
        __half hr = __float2half_rn(v.x);
        __half hi = __float2half_rn(v.y);
        const float s = v.x + v.y;
        __half hs = __float2half_rn(s);
        *(__half*)(smc + XRH_OFF + off) = hr;
        *(__half*)(smc + XRL_OFF + off) = __float2half_rn(v.x - __half2float(hr));
        *(__half*)(smc + XIH_OFF + off) = hi;
        *(__half*)(smc + XIL_OFF + off) = __float2half_rn(v.y - __half2float(hi));
        *(__half*)(smc + XSH_OFF + off) = hs;
        *(__half*)(smc + YSL_OFF + off) = __float2half_rn(s - __half2float(hs));
    }
    __syncthreads();

    // lane geometry
    const int eg = lane >> 2, ec = lane & 3;

    const uint32_t p1hi = (wid < 8) ? XSH_OFF : XIH_OFF;
    const int gmtA = 2 * wid;        // k1/k2 mtile pair
    const int gmt3 = 32 + wid;       // k3 mtile
    const int cphase = (wid >> 2) & 3;   // stagger phase: differs among warps in one SMSP

    float acc[12][4];

#pragma unroll 1
    for (int t = 0; t <= TT; ++t) {
        const bool t3 = (t == 0);
        const __half* WH = t ? g_WBH : g_WAH;
        const __half* WL = t ? g_WBL : g_WAL;
        const int NC = t ? 16 : 8;
        const int coff = cphase * (NC / 4);
        const uint32_t p1lo = (wid < 8) ? YSL_OFF : XIL_OFF;

        sweep(smc, WH, WL, NC, t3, p1hi, p1lo, acc, gmtA, gmt3, lane, coff);

        if (t == 0) __syncthreads();   // YSL alias: all sweep reads done before kbuf store

        // store k1/k2 to kbuf
        {
            const uint32_t kb = (wid < 8) ? KB1_OFF : KB2_OFF;
            const int mb = (wid < 8) ? 32 * wid : 32 * (wid - 8);
#pragma unroll
            for (int mt = 0; mt < 2; ++mt)
#pragma unroll
                for (int nt = 0; nt < 4; ++nt)
#pragma unroll
                    for (int rg = 0; rg < 2; ++rg) {
                        const int m = mb + 16 * mt + eg + 8 * rg;
                        const uint32_t w = (uint32_t)m * 32 + scol(m, nt * 8 + ec * 2);
                        *(float2*)(smc + kb + w * 4) =
                            make_float2(acc[mt * 4 + nt][rg * 2], acc[mt * 4 + nt][rg * 2 + 1]);
                    }
        }
        __syncthreads();

        // combine + LISTA update: warp owns m in [16*wid, 16*wid+16)
        const float g = gammas[t], e = etas[t];
#pragma unroll
        for (int nt = 0; nt < 4; ++nt)
#pragma unroll
            for (int rg = 0; rg < 2; ++rg) {
                const int m = 16 * wid + eg + rg * 8;
                const int n0 = nt * 8 + ec * 2;
                const uint32_t w = (uint32_t)m * 32 + scol(m, n0);
                const float2 k1v = *(const float2*)(smc + KB1_OFF + w * 4);
                const float2 k2v = *(const float2*)(smc + KB2_OFF + w * 4);
                const float k3a = acc[8 + nt][rg * 2 + 0], k3b = acc[8 + nt][rg * 2 + 1];
                const float bre0 = k1v.x - k2v.x, bre1 = k1v.y - k2v.y;
                const float bim0 = k1v.x + k3a,  bim1 = k1v.y + k3b;
                const uint32_t off = swz64(m, n0 * 2);
                float vre0, vre1, vim0, vim1;
                if (t == 0) {
                    *(float2*)(smc + AYR_OFF + w * 4) = make_float2(bre0, bre1);
                    *(float2*)(smc + AYI_OFF + w * 4) = make_float2(bim0, bim1);
                    vre0 = g * bre0; vre1 = g * bre1;
                    vim0 = g * bim0; vim1 = g * bim1;
                } else {
                    const float2 ar = *(const float2*)(smc + AYR_OFF + w * 4);
                    const float2 ai = *(const float2*)(smc + AYI_OFF + w * 4);
                    float2 fr  = __half22float2(*(const __half2*)(smc + XRH_OFF + off));
                    float2 frl = __half22float2(*(const __half2*)(smc + XRL_OFF + off));
                    float2 fi  = __half22float2(*(const __half2*)(smc + XIH_OFF + off));
                    float2 fil = __half22float2(*(const __half2*)(smc + XIL_OFF + off));
                    vre0 = fmaf(g, ar.x - bre0, fr.x + frl.x);
                    vre1 = fmaf(g, ar.y - bre1, fr.y + frl.y);
                    vim0 = fmaf(g, ai.x - bim0, fi.x + fil.x);
                    vim1 = fmaf(g, ai.y - bim1, fi.y + fil.y);
                }
                const float xr0 = copysignf(fmaxf(fabsf(vre0) - e, 0.0f), vre0);
                const float xr1 = copysignf(fmaxf(fabsf(vre1) - e, 0.0f), vre1);
                const float xi0 = copysignf(fmaxf(fabsf(vim0) - e, 0.0f), vim0);
                const float xi1 = copysignf(fmaxf(fabsf(vim1) - e, 0.0f), vim1);
                // state hi/lo (xr, xi)
                __half h0 = __float2half_rn(xr0), h1 = __float2half_rn(xr1);
                *(__half2*)(smc + XRH_OFF + off) = __halves2half2(h0, h1);
                *(__half2*)(smc + XRL_OFF + off) = __halves2half2(
                    __float2half_rn(xr0 - __half2float(h0)),
                    __float2half_rn(xr1 - __half2float(h1)));
                __half g0 = __float2half_rn(xi0), g1 = __float2half_rn(xi1);
                *(__half2*)(smc + XIH_OFF + off) = __halves2half2(g0, g1);
                *(__half2*)(smc + XIL_OFF + off) = __halves2half2(
                    __float2half_rn(xi0 - __half2float(g0)),
                    __float2half_rn(xi1 - __half2float(g1)));
                // xs hi (MMA operand only)
                *(__half2*)(smc + XSH_OFF + off) = __halves2half2(
                    __float2half_rn(xr0 + xi0), __float2half_rn(xr1 + xi1));
            }
        __syncthreads();
    }

    // output: out[b][m][c], re = XRH+XRL, im = XIH+XIL
    for (int idx = tid; idx < NB * 512; idx += THREADS) {
        const int n = idx >> 9, i = idx & 511, m = i >> 1, cc = i & 1;
        const uint32_t ph = cc ? XIH_OFF : XRH_OFF;
        const uint32_t pl = cc ? XIL_OFF : XRL_OFF;
        const uint32_t off = swz64(m, n * 2);
        const float v = __half2float(*(const __half*)(smc + ph + off))
                      + __half2float(*(const __half*)(smc + pl + off));
        out[(b0 + n) * 512 + i] = v;
    }
}

extern "C" void kernel_launch(void* const* d_in, const int* in_sizes, int n_in,
                              void* d_out, int out_size) {
    const float* y      = (const float*)d_in[0];
    const float* A      = (const float*)d_in[1];
    const float* B      = (const float*)d_in[2];
    const float* etas   = (const float*)d_in[3];
    const float* gammas = (const float*)d_in[4];
    float* out = (float*)d_out;

    prep_kernel<<<576, 512>>>(A, B);

    cudaFuncSetAttribute(lista_main, cudaFuncAttributeMaxDynamicSharedMemorySize, SMEM_TOTAL);
    lista_main<<<NCTA, THREADS, SMEM_TOTAL>>>(y, etas, gammas, out);
}

// round 13
// speedup vs baseline: 1.5921x; 1.5921x over previous
#include <cuda_runtime.h>
#include <cuda_fp16.h>
#include <cstdint>

#define TT        10
#define NB        32
#define THREADS   512
#define NCTA      (65536 / NB)       // 2048

// smem layout (bytes)
#define XRH_OFF   0                  // hi planes: 256 k-rows x 32 n x 2B = 16KB each
#define XIH_OFF   16384
#define XRL_OFF   32768              // lo planes
#define XIL_OFF   49152
#define KB1_OFF   65536              // k1: 256 x 32 fp32 (scol-shifted)
#define KB2_OFF   98304              // k2
#define AYR_OFF   131072             // Ay fp32
#define AYI_OFF   163840
#define SMEM_TOTAL 196608            // 192KB

// Gauss-stacked weights, MMA fragment order:
// uint4 index ((chunk16*48 + gmt)*32 + lane); gmt [0,48): m 0-255 Br, 256-511 Br+Bi, 512-767 Bi-Br
__device__ __half g_WBH[196608];   // 384KB (16 chunks x 48 mtiles)
__device__ __half g_WBL[196608];
__device__ __half g_WAH[98304];    // 192KB (8 chunks x 48 mtiles)
__device__ __half g_WAL[98304];

// ---------------- PTX helpers ----------------
static __device__ __forceinline__ uint32_t smem_u32(const void* p) {
    uint32_t a;
    asm("{ .reg .u64 t; cvta.to.shared.u64 t, %1; cvt.u32.u64 %0, t; }" : "=r"(a) : "l"(p));
    return a;
}
static __device__ __forceinline__ void ldmB4(uint32_t* r, uint32_t addr) {
    asm volatile("ldmatrix.sync.aligned.m8n8.x4.trans.shared.b16 {%0,%1,%2,%3}, [%4];"
                 : "=r"(r[0]), "=r"(r[1]), "=r"(r[2]), "=r"(r[3]) : "r"(addr));
}
static __device__ __forceinline__ void mma16816(float* d, const uint32_t* a, const uint32_t* b) {
    asm volatile("mma.sync.aligned.m16n8k16.row.col.f32.f16.f16.f32 "
                 "{%0,%1,%2,%3}, {%4,%5,%6,%7}, {%8,%9}, {%0,%1,%2,%3};"
                 : "+f"(d[0]), "+f"(d[1]), "+f"(d[2]), "+f"(d[3])
                 : "r"(a[0]), "r"(a[1]), "r"(a[2]), "r"(a[3]), "r"(b[0]), "r"(b[1]));
}
static __device__ __forceinline__ uint32_t hadd2u(uint32_t a, uint32_t b) {
    __half2 r = __hadd2(*(__half2*)&a, *(__half2*)&b);
    return *(uint32_t*)&r;
}
// Swizzle for 64B rows (hi/lo planes)
static __device__ __host__ __forceinline__ uint32_t swz64(int row, int colbyte) {
    return (uint32_t)(row * 64 + (colbyte ^ ((row & 6) << 3)));
}
// fp32 scratch column shift: word index within a 32-word row
static __device__ __forceinline__ uint32_t scol(int m, int n0) {
    return (uint32_t)((n0 + ((m & 3) << 3)) & 31);
}

// ---------------- prep: Gauss-stacked W', fp16 hi/lo fragment order ----------------
__global__ void prep_kernel(const float* __restrict__ A, const float* __restrict__ B) {
    const int NBEL = 768 * 256, NAEL = 768 * 128;
    for (int i = blockIdx.x * blockDim.x + threadIdx.x; i < NBEL + NAEL;
         i += gridDim.x * blockDim.x) {
        int R, k;
        float w;
        __half *dH, *dL;
        if (i < NBEL) {
            R = i >> 8; k = i & 255;
            const int grp = R >> 8, m = R & 255;
            const float br = B[m * 256 + k], bi = B[65536 + m * 256 + k];
            w = (grp == 0) ? br : ((grp == 1) ? br + bi : bi - br);
            dH = g_WBH; dL = g_WBL;
        } else {
            const int j = i - NBEL;
            R = j >> 7; k = j & 127;
            const int grp = R >> 8, m = R & 255;
            const float ar = A[m * 128 + k], ai = A[32768 + m * 128 + k];
            w = (grp == 0) ? ar : ((grp == 1) ? ar + ai : ai - ar);
            dH = g_WAH; dL = g_WAL;
        }
        const int gmt = R >> 4, row = R & 15, chunk = k >> 4, kk = k & 15;
        const int rr = (row >> 3) | ((kk >> 3) << 1);
        const int t = (kk & 7) >> 1, pos = kk & 1;
        const int lane = (row & 7) * 4 + t;
        const int dest = ((chunk * 48 + gmt) * 32 + lane) * 8 + rr * 2 + pos;
        __half hi = __float2half_rn(w);
        dH[dest] = hi;
        dL[dest] = __float2half_rn(w - __half2float(hi));
    }
}

// load 6 A fragments (hi mtA, mtA+1, mt3; lo same) for K16 chunk c
static __device__ __forceinline__ void ldA6(uint4* A, const uint4* gH, const uint4* gL,
                                            int iA, int i3, int c) {
    const int o = c * (48 * 32);
    A[0] = __ldg(gH + iA + o); A[1] = __ldg(gH + iA + o + 32); A[2] = __ldg(gH + i3 + o);
    A[3] = __ldg(gL + iA + o); A[4] = __ldg(gL + iA + o + 32); A[5] = __ldg(gL + i3 + o);
}

// ---------------- merged sweep: 3 mtiles/warp, xs computed in-register ----------------
// acc[12][4]: [0..7] = k1-or-k2 (gmtA, gmtA+1); [8..11] = k3 (gmt3)
static __device__ __forceinline__ void sweep(
    const char* smc, const __half* gHh, const __half* gLh, int NC, bool term3, bool k1w,
    float (*acc)[4], int iA, int i3, int lane, uint4* A0, uint4* A1)
{
    const uint4* gH = (const uint4*)gHh;
    const uint4* gL = (const uint4*)gLh;
    const uint32_t smb = smem_u32(smc);
    const uint32_t bxor = (uint32_t)((lane & 6) << 3);
    const uint32_t brow = ((uint32_t)(lane & 7) + ((uint32_t)((lane >> 3) & 1)) * 8) * 64;
    const uint32_t bcol0 = (((uint32_t)(lane >> 4) * 16)) ^ bxor;
    const uint32_t bcol1 = (32u + (uint32_t)(lane >> 4) * 16) ^ bxor;

#pragma unroll
    for (int i = 0; i < 12; ++i)
#pragma unroll
        for (int j = 0; j < 4; ++j) acc[i][j] = 0.0f;

#pragma unroll 1
    for (int c = 0; c < NC; c += 2) {
#pragma unroll
        for (int half = 0; half < 2; ++half) {
            const uint4* Ar = half ? A1 : A0;
            const uint32_t co = (uint32_t)(c + half) << 10;
            // hi fragments: xr and xi
            uint32_t br[8], bi[8];
            ldmB4(br,     smb + XRH_OFF + co + brow + bcol0);
            ldmB4(br + 4, smb + XRH_OFF + co + brow + bcol1);
            ldmB4(bi,     smb + XIH_OFF + co + brow + bcol0);
            ldmB4(bi + 4, smb + XIH_OFF + co + brow + bcol1);
            // k3 MMAs first (br live): Wh then Wl
#pragma unroll
            for (int nt = 0; nt < 4; ++nt)
                mma16816(acc[8 + nt], (const uint32_t*)&Ar[2], &br[nt * 2]);
#pragma unroll
            for (int nt = 0; nt < 4; ++nt)
                mma16816(acc[8 + nt], (const uint32_t*)&Ar[5], &br[nt * 2]);
            // plane-1 operand: k1 warps use xs = xr+xi (in-place into bi), k2 warps use xi
            if (k1w) {
#pragma unroll
                for (int j = 0; j < 8; ++j) bi[j] = hadd2u(br[j], bi[j]);
            }
#pragma unroll
            for (int nt = 0; nt < 4; ++nt) {
                mma16816(acc[nt],     (const uint32_t*)&Ar[0], &bi[nt * 2]); // Wh*b1
                mma16816(acc[4 + nt], (const uint32_t*)&Ar[1], &bi[nt * 2]);
            }
#pragma unroll
            for (int nt = 0; nt < 4; ++nt) {
                mma16816(acc[nt],     (const uint32_t*)&Ar[3], &bi[nt * 2]); // Wl*b1
                mma16816(acc[4 + nt], (const uint32_t*)&Ar[4], &bi[nt * 2]);
            }
            if (term3) {
                // lo fragments (pass 0 only): full 3-term precision for Ay
                uint32_t brl[8], bil[8];
                ldmB4(brl,     smb + XRL_OFF + co + brow + bcol0);
                ldmB4(brl + 4, smb + XRL_OFF + co + brow + bcol1);
                ldmB4(bil,     smb + XIL_OFF + co + brow + bcol0);
                ldmB4(bil + 4, smb + XIL_OFF + co + brow + bcol1);
#pragma unroll
                for (int nt = 0; nt < 4; ++nt)
                    mma16816(acc[8 + nt], (const uint32_t*)&Ar[2], &brl[nt * 2]); // k3: Wh*b3l
                if (k1w) {
#pragma unroll
                    for (int j = 0; j < 8; ++j) bil[j] = hadd2u(brl[j], bil[j]);
                }
#pragma unroll
                for (int nt = 0; nt < 4; ++nt) {
                    mma16816(acc[nt],     (const uint32_t*)&Ar[0], &bil[nt * 2]); // Wh*b1l
                    mma16816(acc[4 + nt], (const uint32_t*)&Ar[1], &bil[nt * 2]);
                }
            }
            // prefetch this buffer's next chunk (within pass)
            const int pf = c + half + 2;
            if (pf < NC) ldA6(half ? A1 : A0, gH, gL, iA, i3, pf);
        }
    }
}

// ---------------- main fused kernel ----------------
__global__ __launch_bounds__(THREADS, 1)
void lista_main(const float* __restrict__ y,
                const float* __restrict__ etas,
                const float* __restrict__ gammas,
                float* __restrict__ out) {
    extern __shared__ char smc[];
    const int tid = threadIdx.x, lane = tid & 31, wid = tid >> 5;
    const long b0 = (long)blockIdx.x * NB;

    // stage y: yr -> XRH/XRL, yi -> XIH/XIL
    const float2* y2 = (const float2*)y;
    for (int idx = tid; idx < NB * 128; idx += THREADS) {
        const int n = idx >> 7, q = idx & 127;
        const float2 v = y2[(b0 + n) * 128 + q];
        const uint32_t off = swz64(q, n * 2);
        __half hr = __float2half_rn(v.x);
        __half hi = __float2half_rn(v.y);
        *(__half*)(smc + XRH_OFF + off) = hr;
        *(__half*)(smc + XRL_OFF + off) = __float2half_rn(v.x - __half2float(hr));
        *(__half*)(smc + XIH_OFF + off) = hi;
        *(__half*)(smc + XIL_OFF + off) = __float2half_rn(v.y - __half2float(hi));
    }
    __syncthreads();

    // lane geometry
    const int eg = lane >> 2, ec = lane & 3;
    const bool k1w = (wid < 8);
    const int gmtA = 2 * wid;        // k1/k2 mtile pair
    const int gmt3 = 32 + wid;       // k3 mtile
    const int iA = gmtA * 32 + lane, i3 = gmt3 * 32 + lane;

    float acc[12][4];
    uint4 A0[6], A1[6];
    ldA6(A0, (const uint4*)g_WAH, (const uint4*)g_WAL, iA, i3, 0);
    ldA6(A1, (const uint4*)g_WAH, (const uint4*)g_WAL, iA, i3, 1);

#pragma unroll 1
    for (int t = 0; t <= TT; ++t) {
        const bool t3 = (t == 0);
        const __half* WH = t ? g_WBH : g_WAH;
        const __half* WL = t ? g_WBL : g_WAL;
        const int NC = t ? 16 : 8;

        sweep(smc, WH, WL, NC, t3, k1w, acc, iA, i3, lane, A0, A1);

        // cross-pass A prefetch: hide next pass's cold-start LDGs under the epilogue
        if (t < TT) {
            ldA6(A0, (const uint4*)g_WBH, (const uint4*)g_WBL, iA, i3, 0);
            ldA6(A1, (const uint4*)g_WBH, (const uint4*)g_WBL, iA, i3, 1);
        }

        // store k1/k2 to kbuf
        {
            const uint32_t kb = k1w ? KB1_OFF : KB2_OFF;
            const int mb = k1w ? 32 * wid : 32 * (wid - 8);
#pragma unroll
            for (int mt = 0; mt < 2; ++mt)
#pragma unroll
                for (int nt = 0; nt < 4; ++nt)
#pragma unroll
                    for (int rg = 0; rg < 2; ++rg) {
                        const int m = mb + 16 * mt + eg + 8 * rg;
                        const uint32_t w = (uint32_t)m * 32 + scol(m, nt * 8 + ec * 2);
                        *(float2*)(smc + kb + w * 4) =
                            make_float2(acc[mt * 4 + nt][rg * 2], acc[mt * 4 + nt][rg * 2 + 1]);
                    }
        }
        __syncthreads();

        // combine + LISTA update: warp owns m in [16*wid, 16*wid+16)
        const float g = gammas[t], e = etas[t];
#pragma unroll
        for (int nt = 0; nt < 4; ++nt)
#pragma unroll
            for (int rg = 0; rg < 2; ++rg) {
                const int m = 16 * wid + eg + rg * 8;
                const int n0 = nt * 8 + ec * 2;
                const uint32_t w = (uint32_t)m * 32 + scol(m, n0);
                const float2 k1v = *(const float2*)(smc + KB1_OFF + w * 4);
                const float2 k2v = *(const float2*)(smc + KB2_OFF + w * 4);
                const float k3a = acc[8 + nt][rg * 2 + 0], k3b = acc[8 + nt][rg * 2 + 1];
                const float bre0 = k1v.x - k2v.x, bre1 = k1v.y - k2v.y;
                const float bim0 = k1v.x + k3a,  bim1 = k1v.y + k3b;
                const uint32_t off = swz64(m, n0 * 2);
                float vre0, vre1, vim0, vim1;
                if (t == 0) {
                    *(float2*)(smc + AYR_OFF + w * 4) = make_float2(bre0, bre1);
                    *(float2*)(smc + AYI_OFF + w * 4) = make_float2(bim0, bim1);
                    vre0 = g * bre0; vre1 = g * bre1;
                    vim0 = g * bim0; vim1 = g * bim1;
                } else {
                    const float2 ar = *(const float2*)(smc + AYR_OFF + w * 4);
                    const float2 ai = *(const float2*)(smc + AYI_OFF + w * 4);
                    float2 fr  = __half22float2(*(const __half2*)(smc + XRH_OFF + off));
                    float2 frl = __half22float2(*(const __half2*)(smc + XRL_OFF + off));
                    float2 fi  = __half22float2(*(const __half2*)(smc + XIH_OFF + off));
                    float2 fil = __half22float2(*(const __half2*)(smc + XIL_OFF + off));
                    vre0 = fmaf(g, ar.x - bre0, fr.x + frl.x);
                    vre1 = fmaf(g, ar.y - bre1, fr.y + frl.y);
                    vim0 = fmaf(g, ai.x - bim0, fi.x + fil.x);
                    vim1 = fmaf(g, ai.y - bim1, fi.y + fil.y);
                }
                const float xr0 = copysignf(fmaxf(fabsf(vre0) - e, 0.0f), vre0);
                const float xr1 = copysignf(fmaxf(fabsf(vre1) - e, 0.0f), vre1);
                const float xi0 = copysignf(fmaxf(fabsf(vim0) - e, 0.0f), vim0);
                const float xi1 = copysignf(fmaxf(fabsf(vim1) - e, 0.0f), vim1);
                // state hi/lo (xr, xi); xs is computed in-register during the sweep
                __half h0 = __float2half_rn(xr0), h1 = __float2half_rn(xr1);
                *(__half2*)(smc + XRH_OFF + off) = __halves2half2(h0, h1);
                *(__half2*)(smc + XRL_OFF + off) = __halves2half2(
                    __float2half_rn(xr0 - __half2float(h0)),
                    __float2half_rn(xr1 - __half2float(h1)));
                __half g0 = __float2half_rn(xi0), g1 = __float2half_rn(xi1);
                *(__half2*)(smc + XIH_OFF + off) = __halves2half2(g0, g1);
                *(__half2*)(smc + XIL_OFF + off) = __halves2half2(
                    __float2half_rn(xi0 - __half2float(g0)),
                    __float2half_rn(xi1 - __half2float(g1)));
            }
        __syncthreads();
    }

    // output: out[b][m][c], re = XRH+XRL, im = XIH+XIL
    for (int idx = tid; idx < NB * 512; idx += THREADS) {
        const int n = idx >> 9, i = idx & 511, m = i >> 1, cc = i & 1;
        const uint32_t ph = cc ? XIH_OFF : XRH_OFF;
        const uint32_t pl = cc ? XIL_OFF : XRL_OFF;
        const uint32_t off = swz64(m, n * 2);
        const float v = __half2float(*(const __half*)(smc + ph + off))
                      + __half2float(*(const __half*)(smc + pl + off));
        out[(b0 + n) * 512 + i] = v;
    }
}

extern "C" void kernel_launch(void* const* d_in, const int* in_sizes, int n_in,
                              void* d_out, int out_size) {
    const float* y      = (const float*)d_in[0];
    const float* A      = (const float*)d_in[1];
    const float* B      = (const float*)d_in[2];
    const float* etas   = (const float*)d_in[3];
    const float* gammas = (const float*)d_in[4];
    float* out = (float*)d_out;

    prep_kernel<<<576, 512>>>(A, B);

    cudaFuncSetAttribute(lista_main, cudaFuncAttributeMaxDynamicSharedMemorySize, SMEM_TOTAL);
    lista_main<<<NCTA, THREADS, SMEM_TOTAL>>>(y, etas, gammas, out);
}

// round 14
// speedup vs baseline: 1.7017x; 1.0689x over previous
#include <cuda_runtime.h>
#include <cuda_fp16.h>
#include <cstdint>

#define TT        10
#define NB        32
#define THREADS   512
#define NCTA      (65536 / NB)       // 2048

// smem layout (bytes): two x-state buffers, each 64KB = {XRH,XIH,XRL,XIL} x 16KB
#define BUFS      65536
#define XRH_R     0
#define XIH_R     16384
#define XRL_R     32768
#define XIL_R     49152
#define AYR_OFF   131072             // Ay fp32 (scol-shifted), 32KB each
#define AYI_OFF   163840
#define SMEM_TOTAL 196608            // 192KB

// Gauss-stacked weights, MMA fragment order:
// uint4 index ((chunk16*48 + gmt)*32 + lane); gmt [0,48): m 0-255 Br, 256-511 Br+Bi, 512-767 Bi-Br
__device__ __half g_WBH[196608];   // 384KB (16 chunks x 48 mtiles)
__device__ __half g_WBL[196608];
__device__ __half g_WAH[98304];    // 192KB (8 chunks x 48 mtiles)
__device__ __half g_WAL[98304];

// ---------------- PTX helpers ----------------
static __device__ __forceinline__ uint32_t smem_u32(const void* p) {
    uint32_t a;
    asm("{ .reg .u64 t; cvta.to.shared.u64 t, %1; cvt.u32.u64 %0, t; }" : "=r"(a) : "l"(p));
    return a;
}
static __device__ __forceinline__ void ldmB4(uint32_t* r, uint32_t addr) {
    asm volatile("ldmatrix.sync.aligned.m8n8.x4.trans.shared.b16 {%0,%1,%2,%3}, [%4];"
                 : "=r"(r[0]), "=r"(r[1]), "=r"(r[2]), "=r"(r[3]) : "r"(addr));
}
static __device__ __forceinline__ void mma16816(float* d, const uint32_t* a, const uint32_t* b) {
    asm volatile("mma.sync.aligned.m16n8k16.row.col.f32.f16.f16.f32 "
                 "{%0,%1,%2,%3}, {%4,%5,%6,%7}, {%8,%9}, {%0,%1,%2,%3};"
                 : "+f"(d[0]), "+f"(d[1]), "+f"(d[2]), "+f"(d[3])
                 : "r"(a[0]), "r"(a[1]), "r"(a[2]), "r"(a[3]), "r"(b[0]), "r"(b[1]));
}
static __device__ __forceinline__ uint32_t hadd2u(uint32_t a, uint32_t b) {
    __half2 r = __hadd2(*(__half2*)&a, *(__half2*)&b);
    return *(uint32_t*)&r;
}
// Swizzle for 64B rows (hi/lo planes)
static __device__ __host__ __forceinline__ uint32_t swz64(int row, int colbyte) {
    return (uint32_t)(row * 64 + (colbyte ^ ((row & 6) << 3)));
}
// fp32 scratch column shift: word index within a 32-word row
static __device__ __forceinline__ uint32_t scol(int m, int n0) {
    return (uint32_t)((n0 + ((m & 3) << 3)) & 31);
}

// ---------------- prep: Gauss-stacked W', fp16 hi/lo fragment order ----------------
__global__ void prep_kernel(const float* __restrict__ A, const float* __restrict__ B) {
    const int NBEL = 768 * 256, NAEL = 768 * 128;
    for (int i = blockIdx.x * blockDim.x + threadIdx.x; i < NBEL + NAEL;
         i += gridDim.x * blockDim.x) {
        int R, k;
        float w;
        __half *dH, *dL;
        if (i < NBEL) {
            R = i >> 8; k = i & 255;
            const int grp = R >> 8, m = R & 255;
            const float br = B[m * 256 + k], bi = B[65536 + m * 256 + k];
            w = (grp == 0) ? br : ((grp == 1) ? br + bi : bi - br);
            dH = g_WBH; dL = g_WBL;
        } else {
            const int j = i - NBEL;
            R = j >> 7; k = j & 127;
            const int grp = R >> 8, m = R & 255;
            const float ar = A[m * 128 + k], ai = A[32768 + m * 128 + k];
            w = (grp == 0) ? ar : ((grp == 1) ? ar + ai : ai - ar);
            dH = g_WAH; dL = g_WAL;
        }
        const int gmt = R >> 4, row = R & 15, chunk = k >> 4, kk = k & 15;
        const int rr = (row >> 3) | ((kk >> 3) << 1);
        const int t = (kk & 7) >> 1, pos = kk & 1;
        const int lane = (row & 7) * 4 + t;
        const int dest = ((chunk * 48 + gmt) * 32 + lane) * 8 + rr * 2 + pos;
        __half hi = __float2half_rn(w);
        dH[dest] = hi;
        dL[dest] = __float2half_rn(w - __half2float(hi));
    }
}

// load 6 A fragments (hi k1,k2,k3; lo k1,k2,k3) for K16 chunk c
static __device__ __forceinline__ void ldA6(uint4* A, const uint4* gH, const uint4* gL,
                                            int i1, int i2, int i3, int c) {
    const int o = c * (48 * 32);
    A[0] = __ldg(gH + i1 + o); A[1] = __ldg(gH + i2 + o); A[2] = __ldg(gH + i3 + o);
    A[3] = __ldg(gL + i1 + o); A[4] = __ldg(gL + i2 + o); A[5] = __ldg(gL + i3 + o);
}

// ---------------- warp-local sweep: k1,k2,k3 all for this warp's m-range ----------------
// acc[12][4]: [0..3]=k1 (nt 0..3), [4..7]=k2, [8..11]=k3
static __device__ __forceinline__ void sweep(
    const char* smc, uint32_t rbase, const __half* gHh, const __half* gLh, int NC, bool term3,
    float (*acc)[4], int i1, int i2, int i3, int lane, uint4* A0, uint4* A1)
{
    const uint4* gH = (const uint4*)gHh;
    const uint4* gL = (const uint4*)gLh;
    const uint32_t smb = smem_u32(smc) + rbase;
    const uint32_t bxor = (uint32_t)((lane & 6) << 3);
    const uint32_t brow = ((uint32_t)(lane & 7) + ((uint32_t)((lane >> 3) & 1)) * 8) * 64;
    const uint32_t bcol0 = (((uint32_t)(lane >> 4) * 16)) ^ bxor;
    const uint32_t bcol1 = (32u + (uint32_t)(lane >> 4) * 16) ^ bxor;

#pragma unroll
    for (int i = 0; i < 12; ++i)
#pragma unroll
        for (int j = 0; j < 4; ++j) acc[i][j] = 0.0f;

#pragma unroll 1
    for (int c = 0; c < NC; c += 2) {
#pragma unroll
        for (int half = 0; half < 2; ++half) {
            const uint4* Ar = half ? A1 : A0;
            const uint32_t co = (uint32_t)(c + half) << 10;
            uint32_t br[8], bi[8];
            ldmB4(br,     smb + XRH_R + co + brow + bcol0);
            ldmB4(br + 4, smb + XRH_R + co + brow + bcol1);
            ldmB4(bi,     smb + XIH_R + co + brow + bcol0);
            ldmB4(bi + 4, smb + XIH_R + co + brow + bcol1);
            // k3 = (Bi-Br)*xr  (br live)
#pragma unroll
            for (int nt = 0; nt < 4; ++nt)
                mma16816(acc[8 + nt], (const uint32_t*)&Ar[2], &br[nt * 2]);
#pragma unroll
            for (int nt = 0; nt < 4; ++nt)
                mma16816(acc[8 + nt], (const uint32_t*)&Ar[5], &br[nt * 2]);
            // k2 = (Br+Bi)*xi
#pragma unroll
            for (int nt = 0; nt < 4; ++nt)
                mma16816(acc[4 + nt], (const uint32_t*)&Ar[1], &bi[nt * 2]);
#pragma unroll
            for (int nt = 0; nt < 4; ++nt)
                mma16816(acc[4 + nt], (const uint32_t*)&Ar[4], &bi[nt * 2]);
            // xs = xr + xi in-place, then k1 = Br*xs
#pragma unroll
            for (int j = 0; j < 8; ++j) br[j] = hadd2u(br[j], bi[j]);
#pragma unroll
            for (int nt = 0; nt < 4; ++nt)
                mma16816(acc[nt], (const uint32_t*)&Ar[0], &br[nt * 2]);
#pragma unroll
            for (int nt = 0; nt < 4; ++nt)
                mma16816(acc[nt], (const uint32_t*)&Ar[3], &br[nt * 2]);
            if (term3) {
                // lo-plane operands (pass 0 only): Wh * x_lo for all three terms
                uint32_t brl[8], bil[8];
                ldmB4(brl,     smb + XRL_R + co + brow + bcol0);
                ldmB4(brl + 4, smb + XRL_R + co + brow + bcol1);
                ldmB4(bil,     smb + XIL_R + co + brow + bcol0);
                ldmB4(bil + 4, smb + XIL_R + co + brow + bcol1);
#pragma unroll
                for (int nt = 0; nt < 4; ++nt)
                    mma16816(acc[8 + nt], (const uint32_t*)&Ar[2], &brl[nt * 2]);
#pragma unroll
                for (int nt = 0; nt < 4; ++nt)
                    mma16816(acc[4 + nt], (const uint32_t*)&Ar[1], &bil[nt * 2]);
#pragma unroll
                for (int j = 0; j < 8; ++j) brl[j] = hadd2u(brl[j], bil[j]);
#pragma unroll
                for (int nt = 0; nt < 4; ++nt)
                    mma16816(acc[nt], (const uint32_t*)&Ar[0], &brl[nt * 2]);
            }
            // prefetch this buffer's next chunk (within pass)
            const int pf = c + half + 2;
            if (pf < NC) ldA6(half ? A1 : A0, gH, gL, i1, i2, i3, pf);
        }
    }
}

// ---------------- main fused kernel ----------------
__global__ __launch_bounds__(THREADS, 1)
void lista_main(const float* __restrict__ y,
                const float* __restrict__ etas,
                const float* __restrict__ gammas,
                float* __restrict__ out) {
    extern __shared__ char smc[];
    const int tid = threadIdx.x, lane = tid & 31, wid = tid >> 5;
    const long b0 = (long)blockIdx.x * NB;

    // stage y into buffer 0: yr -> XRH/XRL, yi -> XIH/XIL
    const float2* y2 = (const float2*)y;
    for (int idx = tid; idx < NB * 128; idx += THREADS) {
        const int n = idx >> 7, q = idx & 127;
        const float2 v = y2[(b0 + n) * 128 + q];
        const uint32_t off = swz64(q, n * 2);
        __half hr = __float2half_rn(v.x);
        __half hi = __float2half_rn(v.y);
        *(__half*)(smc + XRH_R + off) = hr;
        *(__half*)(smc + XRL_R + off) = __float2half_rn(v.x - __half2float(hr));
        *(__half*)(smc + XIH_R + off) = hi;
        *(__half*)(smc + XIL_R + off) = __float2half_rn(v.y - __half2float(hi));
    }
    __syncthreads();

    // lane geometry
    const int eg = lane >> 2, ec = lane & 3;
    // warp-local Gauss mtiles: k1 = gmt wid, k2 = gmt 16+wid, k3 = gmt 32+wid
    const int i1 = wid * 32 + lane;
    const int i2 = (16 + wid) * 32 + lane;
    const int i3 = (32 + wid) * 32 + lane;

    float acc[12][4];
    uint4 A0[6], A1[6];
    ldA6(A0, (const uint4*)g_WAH, (const uint4*)g_WAL, i1, i2, i3, 0);
    ldA6(A1, (const uint4*)g_WAH, (const uint4*)g_WAL, i1, i2, i3, 1);

#pragma unroll 1
    for (int t = 0; t <= TT; ++t) {
        const bool t3 = (t == 0);
        const __half* WH = t ? g_WBH : g_WAH;
        const __half* WL = t ? g_WBL : g_WAL;
        const int NC = t ? 16 : 8;
        const uint32_t rb = (uint32_t)(t & 1) * BUFS;        // read buffer
        const uint32_t wb = (uint32_t)(1 - (t & 1)) * BUFS;  // write buffer

        sweep(smc, rb, WH, WL, NC, t3, acc, i1, i2, i3, lane, A0, A1);

        // cross-pass A prefetch: hide next pass's cold-start LDGs under the epilogue
        if (t < TT) {
            ldA6(A0, (const uint4*)g_WBH, (const uint4*)g_WBL, i1, i2, i3, 0);
            ldA6(A1, (const uint4*)g_WBH, (const uint4*)g_WBL, i1, i2, i3, 1);
        }

        // warp-local combine + LISTA update (no barrier before: write buffer is inactive)
        const float g = gammas[t], e = etas[t];
#pragma unroll
        for (int nt = 0; nt < 4; ++nt)
#pragma unroll
            for (int rg = 0; rg < 2; ++rg) {
                const int m = 16 * wid + eg + rg * 8;
                const int n0 = nt * 8 + ec * 2;
                const uint32_t w = (uint32_t)m * 32 + scol(m, n0);
                const float k1a = acc[nt][rg * 2 + 0],     k1b = acc[nt][rg * 2 + 1];
                const float k2a = acc[4 + nt][rg * 2 + 0], k2b = acc[4 + nt][rg * 2 + 1];
                const float k3a = acc[8 + nt][rg * 2 + 0], k3b = acc[8 + nt][rg * 2 + 1];
                const float bre0 = k1a - k2a, bre1 = k1b - k2b;
                const float bim0 = k1a + k3a, bim1 = k1b + k3b;
                const uint32_t off = swz64(m, n0 * 2);
                float vre0, vre1, vim0, vim1;
                if (t == 0) {
                    *(float2*)(smc + AYR_OFF + w * 4) = make_float2(bre0, bre1);
                    *(float2*)(smc + AYI_OFF + w * 4) = make_float2(bim0, bim1);
                    vre0 = g * bre0; vre1 = g * bre1;
                    vim0 = g * bim0; vim1 = g * bim1;
                } else {
                    const float2 ar = *(const float2*)(smc + AYR_OFF + w * 4);
                    const float2 ai = *(const float2*)(smc + AYI_OFF + w * 4);
                    float2 fr  = __half22float2(*(const __half2*)(smc + rb + XRH_R + off));
                    float2 frl = __half22float2(*(const __half2*)(smc + rb + XRL_R + off));
                    float2 fi  = __half22float2(*(const __half2*)(smc + rb + XIH_R + off));
                    float2 fil = __half22float2(*(const __half2*)(smc + rb + XIL_R + off));
                    vre0 = fmaf(g, ar.x - bre0, fr.x + frl.x);
                    vre1 = fmaf(g, ar.y - bre1, fr.y + frl.y);
                    vim0 = fmaf(g, ai.x - bim0, fi.x + fil.x);
                    vim1 = fmaf(g, ai.y - bim1, fi.y + fil.y);
                }
                const float xr0 = copysignf(fmaxf(fabsf(vre0) - e, 0.0f), vre0);
                const float xr1 = copysignf(fmaxf(fabsf(vre1) - e, 0.0f), vre1);
                const float xi0 = copysignf(fmaxf(fabsf(vim0) - e, 0.0f), vim0);
                const float xi1 = copysignf(fmaxf(fabsf(vim1) - e, 0.0f), vim1);
                __half h0 = __float2half_rn(xr0), h1 = __float2half_rn(xr1);
                *(__half2*)(smc + wb + XRH_R + off) = __halves2half2(h0, h1);
                *(__half2*)(smc + wb + XRL_R + off) = __halves2half2(
                    __float2half_rn(xr0 - __half2float(h0)),
                    __float2half_rn(xr1 - __half2float(h1)));
                __half g0 = __float2half_rn(xi0), g1 = __float2half_rn(xi1);
                *(__half2*)(smc + wb + XIH_R + off) = __halves2half2(g0, g1);
                *(__half2*)(smc + wb + XIL_R + off) = __halves2half2(
                    __float2half_rn(xi0 - __half2float(g0)),
                    __float2half_rn(xi1 - __half2float(g1)));
            }
        __syncthreads();   // one barrier per pass: wb visible before next sweep reads it
    }

    // output: pass TT wrote buffer 1
    const char* xf = smc + BUFS;
    for (int idx = tid; idx < NB * 512; idx += THREADS) {
        const int n = idx >> 9, i = idx & 511, m = i >> 1, cc = i & 1;
        const uint32_t ph = cc ? XIH_R : XRH_R;
        const uint32_t pl = cc ? XIL_R : XRL_R;
        const uint32_t off = swz64(m, n * 2);
        const float v = __half2float(*(const __half*)(xf + ph + off))
                      + __half2float(*(const __half*)(xf + pl + off));
        out[(b0 + n) * 512 + i] = v;
    }
}

extern "C" void kernel_launch(void* const* d_in, const int* in_sizes, int n_in,
                              void* d_out, int out_size) {
    const float* y      = (const float*)d_in[0];
    const float* A      = (const float*)d_in[1];
    const float* B      = (const float*)d_in[2];
    const float* etas   = (const float*)d_in[3];
    const float* gammas = (const float*)d_in[4];
    float* out = (float*)d_out;

    prep_kernel<<<576, 512>>>(A, B);

    cudaFuncSetAttribute(lista_main, cudaFuncAttributeMaxDynamicSharedMemorySize, SMEM_TOTAL);
    lista_main<<<NCTA, THREADS, SMEM_TOTAL>>>(y, etas, gammas, out);
}